// round 2
// baseline (speedup 1.0000x reference)
#include <cuda_runtime.h>
#include <math.h>

// ---------------------------------------------------------------------------
// MLP edge predictor, factorized:
//   P[n, 0:128]   = W1[:, 0:128]   @ h[n] + b1      (A, bias folded)
//   P[n, 128:256] = W1[:, 128:256] @ h[n]           (B)
//   out[e] = sigmoid( W2 . relu(A[src[e]] + B[dst[e]]) + b2 )
// Stage 1: tiled fp32 GEMM using packed fma.rn.f32x2 (FFMA2).
// Stage 2: warp-per-edge gather + dot (L2-bound).
// ---------------------------------------------------------------------------

#define NMAX    100000
#define FEATS   128
#define POUT    256

__device__ float g_P[(size_t)NMAX * POUT];   // 102.4 MB scratch (static: no allocs)

typedef unsigned long long u64;

__device__ __forceinline__ u64 ffma2(u64 a, u64 b, u64 c) {
    u64 d;
    asm("fma.rn.f32x2 %0, %1, %2, %3;" : "=l"(d) : "l"(a), "l"(b), "l"(c));
    return d;
}
__device__ __forceinline__ u64 pack2(float x, float y) {
    u64 d;
    asm("mov.b64 %0, {%1, %2};" : "=l"(d) : "f"(x), "f"(y));
    return d;
}
__device__ __forceinline__ void unpack2(u64 v, float& x, float& y) {
    asm("mov.b64 {%0, %1}, %2;" : "=f"(x), "=f"(y) : "l"(v));
}

#define TILE_N  64       // nodes per block
#define TILE_J  128      // outputs per block (one half of 256 via blockIdx.y)
#define TK      32       // k-chunk
#define HPAD    (FEATS ? (TK + 1) : 0)   // sh_h row pad
#define WPAD    (TILE_J + 2)             // sh_w row pad (keeps 8B align for LDS.64)

__global__ __launch_bounds__(128, 4) void proj_kernel(
    const float* __restrict__ h,
    const float* __restrict__ W1,
    const float* __restrict__ b1,
    int nNodes)
{
    __shared__ float sh_h[TILE_N][TK + 1];   // [node][k]
    __shared__ float sh_w[TK][WPAD];         // [k][out]  (k-major: j-pairs contiguous)

    const int half  = blockIdx.y;            // 0 -> A (+b1), 1 -> B
    const int node0 = blockIdx.x * TILE_N;
    const int tid   = threadIdx.x;

    // thread tile: 8 nodes x 8 outputs (outputs packed in f32x2 pairs)
    const int tn = (tid & 7) * 8;            // node offset within tile
    const int tj = (tid >> 3) * 8;           // output offset within tile

    u64 acc2[8][4];
    #pragma unroll
    for (int i = 0; i < 8; i++)
        #pragma unroll
        for (int jp = 0; jp < 4; jp++)
            acc2[i][jp] = pack2(0.f, 0.f);

    for (int kc = 0; kc < FEATS; kc += TK) {
        // ---- load h chunk: 64 nodes x 32 k, float4 per thread x4 ----
        #pragma unroll
        for (int f = tid; f < (TILE_N * TK) / 4; f += 128) {
            int n  = f >> 3;                 // 0..63
            int k4 = (f & 7) * 4;            // 0,4,...,28
            int gn = node0 + n;
            if (gn >= nNodes) gn = nNodes - 1;       // clamp (stores guarded)
            float4 v = *(const float4*)&h[(size_t)gn * FEATS + kc + k4];
            sh_h[n][k4 + 0] = v.x;
            sh_h[n][k4 + 1] = v.y;
            sh_h[n][k4 + 2] = v.z;
            sh_h[n][k4 + 3] = v.w;
        }
        // ---- load W chunk transposed: sh_w[k][j] from W1[j][half*128 + k] ----
        #pragma unroll
        for (int f = tid; f < (TILE_J * TK) / 4; f += 128) {
            int j  = f >> 3;                 // 0..127
            int k4 = (f & 7) * 4;
            float4 v = *(const float4*)&W1[j * (2 * FEATS) + half * FEATS + kc + k4];
            sh_w[k4 + 0][j] = v.x;
            sh_w[k4 + 1][j] = v.y;
            sh_w[k4 + 2][j] = v.z;
            sh_w[k4 + 3][j] = v.w;
        }
        __syncthreads();

        #pragma unroll 8
        for (int k = 0; k < TK; k++) {
            u64 a2[8];
            #pragma unroll
            for (int i = 0; i < 8; i++) {
                float av = sh_h[tn + i][k];
                a2[i] = pack2(av, av);
            }
            #pragma unroll
            for (int jp = 0; jp < 4; jp++) {
                u64 w2 = *(const u64*)&sh_w[k][tj + 2 * jp];
                #pragma unroll
                for (int i = 0; i < 8; i++)
                    acc2[i][jp] = ffma2(a2[i], w2, acc2[i][jp]);
            }
        }
        __syncthreads();
    }

    // ---- epilogue: fold b1 into the A half, store to g_P ----
    #pragma unroll
    for (int i = 0; i < 8; i++) {
        int gn = node0 + tn + i;
        if (gn < nNodes) {
            float vals[8];
            #pragma unroll
            for (int jp = 0; jp < 4; jp++)
                unpack2(acc2[i][jp], vals[2 * jp], vals[2 * jp + 1]);
            if (half == 0) {
                #pragma unroll
                for (int j = 0; j < 8; j++) vals[j] += b1[tj + j];
            }
            float* dst = &g_P[(size_t)gn * POUT + half * TILE_J + tj];
            *(float4*)(dst)     = make_float4(vals[0], vals[1], vals[2], vals[3]);
            *(float4*)(dst + 4) = make_float4(vals[4], vals[5], vals[6], vals[7]);
        }
    }
}

// ---------------------------------------------------------------------------
// Edge stage: one warp per edge. Lane l handles hidden dims [4l, 4l+3].
// ---------------------------------------------------------------------------
__global__ __launch_bounds__(256) void edge_kernel(
    const int*   __restrict__ src,
    const int*   __restrict__ dst,
    const float* __restrict__ W2,
    const float* __restrict__ b2,
    float*       __restrict__ out,
    int E)
{
    const int warp = (int)((blockIdx.x * (unsigned)blockDim.x + threadIdx.x) >> 5);
    const int lane = threadIdx.x & 31;
    if (warp >= E) return;

    const int s = src[warp];
    const int d = dst[warp];

    const float4 a = *(const float4*)&g_P[(size_t)s * POUT + lane * 4];
    const float4 b = *(const float4*)&g_P[(size_t)d * POUT + FEATS + lane * 4];
    const float4 w = *(const float4*)&W2[lane * 4];

    float acc = fmaxf(a.x + b.x, 0.f) * w.x
              + fmaxf(a.y + b.y, 0.f) * w.y
              + fmaxf(a.z + b.z, 0.f) * w.z
              + fmaxf(a.w + b.w, 0.f) * w.w;

    #pragma unroll
    for (int off = 16; off > 0; off >>= 1)
        acc += __shfl_xor_sync(0xFFFFFFFFu, acc, off);

    if (lane == 0) {
        float z = acc + b2[0];
        out[warp] = 1.0f / (1.0f + expf(-z));
    }
}

extern "C" void kernel_launch(void* const* d_in, const int* in_sizes, int n_in,
                              void* d_out, int out_size)
{
    const int*   src = (const int*)  d_in[0];
    const int*   dst = (const int*)  d_in[1];
    const float* h   = (const float*)d_in[2];
    const float* W1  = (const float*)d_in[3];
    const float* b1  = (const float*)d_in[4];
    const float* W2  = (const float*)d_in[5];
    const float* b2  = (const float*)d_in[6];
    float* out = (float*)d_out;

    const int E      = in_sizes[0];
    const int nNodes = in_sizes[2] / FEATS;

    dim3 g1((nNodes + TILE_N - 1) / TILE_N, 2);
    proj_kernel<<<g1, 128>>>(h, W1, b1, nNodes);

    int totalThreads = E * 32;
    edge_kernel<<<(totalThreads + 255) / 256, 256>>>(src, dst, W2, b2, out, E);
}

// round 12
// speedup vs baseline: 1.5059x; 1.5059x over previous
#include <cuda_runtime.h>
#include <cuda_fp16.h>
#include <cuda_bf16.h>
#include <math.h>
#include <stdint.h>

#define NMAX  100000
#define FEATS 128
#define POUT  256

// fp16 projected features: [n][0:128]=A(+b1), [n][128:256]=B   (51.2 MB)
__device__ __align__(16) __half g_Ph[(size_t)NMAX * POUT];

// ---------------------------------------------------------------- helpers
__device__ __forceinline__ uint32_t smem_u32(const void* p) {
    return (uint32_t)__cvta_generic_to_shared(p);
}

#define LDSM_X4(r, addr)                                                      \
    asm volatile("ldmatrix.sync.aligned.m8n8.x4.shared.b16 {%0,%1,%2,%3}, [%4];" \
        : "=r"((r)[0]), "=r"((r)[1]), "=r"((r)[2]), "=r"((r)[3]) : "r"(addr))

__device__ __forceinline__ void mma_bf16(float* d, const uint32_t* a,
                                         const uint32_t* b) {
    asm volatile(
        "mma.sync.aligned.m16n8k16.row.col.f32.bf16.bf16.f32 "
        "{%0,%1,%2,%3}, {%4,%5,%6,%7}, {%8,%9}, {%0,%1,%2,%3};"
        : "+f"(d[0]), "+f"(d[1]), "+f"(d[2]), "+f"(d[3])
        : "r"(a[0]), "r"(a[1]), "r"(a[2]), "r"(a[3]), "r"(b[0]), "r"(b[1]));
}

// -------------------------------------------------------------- proj (HMMA)
// Per CTA: 128 nodes x 128 outputs (jb = blockIdx.y picks W1 col half).
// SMEM tiles padded row-major bf16, stride 136 elems (272 B -> ldmatrix
// 8-row groups conflict-free). hi/lo split, 3 MMA passes, fp32 accum.
#define TILE_M  128
#define STRIDE  136                       // row stride in bf16 elements
#define BUF_BYTES (128 * STRIDE * 2)      // 34816 per buffer

#define SO_B1   0
#define SO_AHI  512
#define SO_ALO  (SO_AHI + BUF_BYTES)
#define SO_BHI  (SO_ALO + BUF_BYTES)
#define SO_BLO  (SO_BHI + BUF_BYTES)
#define SMEM_TOTAL (SO_BLO + BUF_BYTES)

// Convert row r, k-halfchunk kh (64 fp32) into bf16 hi/lo padded buffers.
__device__ __forceinline__ void conv_rows(int r, int kh,
                                          const float* __restrict__ src,
                                          char* dhi, char* dlo)
{
    const int base = r * STRIDE + kh * 64;    // element offset
    #pragma unroll
    for (int g = 0; g < 8; g++) {
        float4 v0 = *(const float4*)(src + g * 8);
        float4 v1 = *(const float4*)(src + g * 8 + 4);
        float f[8] = {v0.x, v0.y, v0.z, v0.w, v1.x, v1.y, v1.z, v1.w};
        __align__(16) __nv_bfloat16 hi[8];
        __align__(16) __nv_bfloat16 lo[8];
        #pragma unroll
        for (int q = 0; q < 8; q++) {
            hi[q] = __float2bfloat16_rn(f[q]);
            lo[q] = __float2bfloat16_rn(f[q] - __bfloat162float(hi[q]));
        }
        *(uint4*)(dhi + (base + g * 8) * 2) = *(uint4*)hi;
        *(uint4*)(dlo + (base + g * 8) * 2) = *(uint4*)lo;
    }
}

__global__ __launch_bounds__(256, 1) void proj_mma(
    const float* __restrict__ h,
    const float* __restrict__ W1,
    const float* __restrict__ b1,
    int nNodes)
{
    extern __shared__ char smem[];
    const int tid  = threadIdx.x;
    const int wid  = tid >> 5;
    const int lane = tid & 31;
    const int gid  = lane >> 2;
    const int tig  = lane & 3;
    const int jb   = blockIdx.y;            // 0 -> A half (+b1), 1 -> B half
    const int tile = blockIdx.x;

    // ---- b1 to smem (jb==0 only reads it) ----
    if (tid < 128)
        ((float*)(smem + SO_B1))[tid] = b1[tid];

    // ---- convert W block: 128 j-rows x 128 k (cols jb*128..+128) ----
    {
        int r  = tid >> 1;
        int kh = tid & 1;
        conv_rows(r, kh, W1 + r * 256 + jb * 128 + kh * 64,
                  smem + SO_BHI, smem + SO_BLO);
    }
    // ---- convert A tile: 128 nodes x 128 k ----
    {
        int r  = tid >> 1;
        int kh = tid & 1;
        int gn = tile * TILE_M + r;
        if (gn >= nNodes) gn = nNodes - 1;
        conv_rows(r, kh, h + (size_t)gn * FEATS + kh * 64,
                  smem + SO_AHI, smem + SO_ALO);
    }
    __syncthreads();

    // warp tile: m0 = (wid&3)*32, n0 = (wid>>2)*64
    const int m0 = (wid & 3) * 32;
    const int n0 = (wid >> 2) * 64;

    // per-lane ldmatrix element offsets (k-chunk adds kc*16)
    // A (x4 covers m16 x k16): row = m_base + (lane&15), col = ((lane>>4)<<3)
    int aoff[2];
    #pragma unroll
    for (int mt = 0; mt < 2; mt++)
        aoff[mt] = (m0 + mt * 16 + (lane & 15)) * STRIDE + ((lane >> 4) << 3);
    // B (x4 covers 2 n-tiles x k16): row = n_base + ((lane>>4)<<3) + (lane&7),
    //                                col = (((lane>>3)&1)<<3)
    int boff[4];
    #pragma unroll
    for (int p = 0; p < 4; p++)
        boff[p] = (n0 + p * 16 + ((lane >> 4) << 3) + (lane & 7)) * STRIDE
                + (((lane >> 3) & 1) << 3);

    float acc[2][8][4];
    #pragma unroll
    for (int mt = 0; mt < 2; mt++)
        #pragma unroll
        for (int nt = 0; nt < 8; nt++)
            #pragma unroll
            for (int q = 0; q < 4; q++)
                acc[mt][nt][q] = 0.f;

    const uint32_t ahi = smem_u32(smem + SO_AHI);
    const uint32_t alo = smem_u32(smem + SO_ALO);
    const uint32_t bhi = smem_u32(smem + SO_BHI);
    const uint32_t blo = smem_u32(smem + SO_BLO);

    #pragma unroll
    for (int pass = 0; pass < 3; pass++) {
        const uint32_t abase = (pass == 2) ? alo : ahi;   // lo*hi on pass 2
        const uint32_t bbase = (pass == 1) ? blo : bhi;   // hi*lo on pass 1
        #pragma unroll
        for (int kc = 0; kc < 8; kc++) {
            const int k0 = kc * 16;
            uint32_t a[2][4];
            #pragma unroll
            for (int mt = 0; mt < 2; mt++)
                LDSM_X4(a[mt], abase + (uint32_t)(aoff[mt] + k0) * 2);
            uint32_t b[4][4];
            #pragma unroll
            for (int p = 0; p < 4; p++)
                LDSM_X4(b[p], bbase + (uint32_t)(boff[p] + k0) * 2);
            #pragma unroll
            for (int mt = 0; mt < 2; mt++)
                #pragma unroll
                for (int p = 0; p < 4; p++) {
                    mma_bf16(acc[mt][2 * p],     a[mt], &b[p][0]);
                    mma_bf16(acc[mt][2 * p + 1], a[mt], &b[p][2]);
                }
        }
    }

    // ---- epilogue: +b1 (jb==0), fp16 store to g_Ph ----
    const float* sb1 = (const float*)(smem + SO_B1);
    #pragma unroll
    for (int nt = 0; nt < 8; nt++) {
        const int j = n0 + nt * 8 + 2 * tig;             // even
        float bx = 0.f, by = 0.f;
        if (jb == 0) { bx = sb1[j]; by = sb1[j + 1]; }
        #pragma unroll
        for (int mt = 0; mt < 2; mt++) {
            const int node0 = tile * TILE_M + m0 + mt * 16 + gid;
            float* c = acc[mt][nt];
            if (node0 < nNodes) {
                __half2 hv = __floats2half2_rn(c[0] + bx, c[1] + by);
                *(__half2*)(g_Ph + (size_t)node0 * POUT + jb * 128 + j) = hv;
            }
            if (node0 + 8 < nNodes) {
                __half2 hv = __floats2half2_rn(c[2] + bx, c[3] + by);
                *(__half2*)(g_Ph + (size_t)(node0 + 8) * POUT + jb * 128 + j) = hv;
            }
        }
    }
}

// ------------------------------------------------------------------ edge stage
// 2 edges per warp; 16 lanes each, lane l covers hidden dims [8l, 8l+7].
__global__ __launch_bounds__(256) void edge_kernel(
    const int*   __restrict__ src,
    const int*   __restrict__ dst,
    const float* __restrict__ W2,
    const float* __restrict__ b2,
    float*       __restrict__ out,
    int E)
{
    const int gw   = (int)((blockIdx.x * 256u + threadIdx.x) >> 5);
    const int lane = threadIdx.x & 31;
    const int sub  = lane >> 4;
    const int l    = lane & 15;

    int e = gw * 2 + sub;
    const bool valid = (e < E);
    if (gw * 2 >= E) return;          // whole warp out of range
    if (e >= E) e = E - 1;            // keep warp converged for shfl

    float w[8];
    #pragma unroll
    for (int q = 0; q < 8; q++) w[q] = W2[l * 8 + q];

    const int s = src[e];
    const int d = dst[e];

    const uint4 pa = *(const uint4*)(g_Ph + (size_t)s * POUT + l * 8);
    const uint4 pb = *(const uint4*)(g_Ph + (size_t)d * POUT + 128 + l * 8);

    const __half2* ha = (const __half2*)&pa;
    const __half2* hb = (const __half2*)&pb;

    float acc = 0.f;
    #pragma unroll
    for (int q = 0; q < 4; q++) {
        float2 fa = __half22float2(ha[q]);
        float2 fb = __half22float2(hb[q]);
        acc = fmaf(fmaxf(fa.x + fb.x, 0.f), w[2 * q],     acc);
        acc = fmaf(fmaxf(fa.y + fb.y, 0.f), w[2 * q + 1], acc);
    }

    #pragma unroll
    for (int off = 8; off > 0; off >>= 1)
        acc += __shfl_down_sync(0xFFFFFFFFu, acc, off, 16);

    if (l == 0 && valid) {
        float z = acc + b2[0];
        out[e] = 1.0f / (1.0f + __expf(-z));
    }
}

// ---------------------------------------------------------------------- launch
extern "C" void kernel_launch(void* const* d_in, const int* in_sizes, int n_in,
                              void* d_out, int out_size)
{
    const int*   src = (const int*)  d_in[0];
    const int*   dst = (const int*)  d_in[1];
    const float* h   = (const float*)d_in[2];
    const float* W1  = (const float*)d_in[3];
    const float* b1  = (const float*)d_in[4];
    const float* W2  = (const float*)d_in[5];
    const float* b2  = (const float*)d_in[6];
    float* out = (float*)d_out;

    const int E      = in_sizes[0];
    const int nNodes = in_sizes[2] / FEATS;
    const int nTiles = (nNodes + TILE_M - 1) / TILE_M;

    cudaFuncSetAttribute(proj_mma, cudaFuncAttributeMaxDynamicSharedMemorySize, SMEM_TOTAL);
    proj_mma<<<dim3(nTiles, 2), 256, SMEM_TOTAL>>>(h, W1, b1, nNodes);

    const int nWarps  = (E + 1) / 2;
    const int nBlocks = (nWarps + 7) / 8;
    edge_kernel<<<nBlocks, 256>>>(src, dst, W2, b2, out, E);
}

// round 13
// speedup vs baseline: 2.0599x; 1.3679x over previous
#include <cuda_runtime.h>
#include <cuda_fp16.h>
#include <cuda_bf16.h>
#include <math.h>
#include <stdint.h>

#define NMAX  100000
#define FEATS 128
#define POUT  256

// fp16 projected features: [n][0:128]=A(+b1), [n][128:256]=B   (51.2 MB)
__device__ __align__(16) __half g_Ph[(size_t)NMAX * POUT];

// ---------------------------------------------------------------- helpers
__device__ __forceinline__ uint32_t smem_u32(const void* p) {
    return (uint32_t)__cvta_generic_to_shared(p);
}

#define LDSM_X4(r, addr)                                                      \
    asm volatile("ldmatrix.sync.aligned.m8n8.x4.shared.b16 {%0,%1,%2,%3}, [%4];" \
        : "=r"((r)[0]), "=r"((r)[1]), "=r"((r)[2]), "=r"((r)[3]) : "r"(addr))

__device__ __forceinline__ void mma_f16(float* d, const uint32_t* a,
                                        const uint32_t* b) {
    asm volatile(
        "mma.sync.aligned.m16n8k16.row.col.f32.f16.f16.f32 "
        "{%0,%1,%2,%3}, {%4,%5,%6,%7}, {%8,%9}, {%0,%1,%2,%3};"
        : "+f"(d[0]), "+f"(d[1]), "+f"(d[2]), "+f"(d[3])
        : "r"(a[0]), "r"(a[1]), "r"(a[2]), "r"(a[3]), "r"(b[0]), "r"(b[1]));
}

// -------------------------------------------------------------- proj (HMMA)
// Per CTA: 128 nodes x 128 outputs (jb = blockIdx.y picks W1 col half).
// SMEM tiles padded row-major fp16, stride 136 elems (272 B -> ldmatrix
// 8-row groups conflict-free). Single-pass fp16 MMA, fp32 accum.
#define TILE_M  128
#define STRIDE  136                       // row stride in fp16 elements
#define BUF_BYTES (128 * STRIDE * 2)      // 34816 per buffer

#define SO_B1   0
#define SO_A    512
#define SO_B    (SO_A + BUF_BYTES)
#define SMEM_TOTAL (SO_B + BUF_BYTES)     // 70144 -> 2 CTAs/SM

// Convert row r, k-halfchunk kh (64 fp32) into fp16 padded buffer.
__device__ __forceinline__ void conv_rows16(int r, int kh,
                                            const float* __restrict__ src,
                                            char* dst)
{
    const int base = r * STRIDE + kh * 64;    // element offset
    #pragma unroll
    for (int g = 0; g < 8; g++) {
        float4 v0 = *(const float4*)(src + g * 8);
        float4 v1 = *(const float4*)(src + g * 8 + 4);
        __align__(16) __half2 hv[4];
        hv[0] = __floats2half2_rn(v0.x, v0.y);
        hv[1] = __floats2half2_rn(v0.z, v0.w);
        hv[2] = __floats2half2_rn(v1.x, v1.y);
        hv[3] = __floats2half2_rn(v1.z, v1.w);
        *(uint4*)(dst + (base + g * 8) * 2) = *(uint4*)hv;
    }
}

__global__ __launch_bounds__(256, 2) void proj_mma(
    const float* __restrict__ h,
    const float* __restrict__ W1,
    const float* __restrict__ b1,
    int nNodes)
{
    extern __shared__ char smem[];
    const int tid  = threadIdx.x;
    const int wid  = tid >> 5;
    const int lane = tid & 31;
    const int gid  = lane >> 2;
    const int tig  = lane & 3;
    const int jb   = blockIdx.y;            // 0 -> A half (+b1), 1 -> B half
    const int tile = blockIdx.x;

    if (tid < 128)
        ((float*)(smem + SO_B1))[tid] = b1[tid];

    // ---- convert W block: 128 j-rows x 128 k (cols jb*128..+128) ----
    {
        int r  = tid >> 1;
        int kh = tid & 1;
        conv_rows16(r, kh, W1 + r * 256 + jb * 128 + kh * 64, smem + SO_B);
    }
    // ---- convert A tile: 128 nodes x 128 k ----
    {
        int r  = tid >> 1;
        int kh = tid & 1;
        int gn = tile * TILE_M + r;
        if (gn >= nNodes) gn = nNodes - 1;
        conv_rows16(r, kh, h + (size_t)gn * FEATS + kh * 64, smem + SO_A);
    }
    __syncthreads();

    // warp tile: m0 = (wid&3)*32, n0 = (wid>>2)*64
    const int m0 = (wid & 3) * 32;
    const int n0 = (wid >> 2) * 64;

    // per-lane ldmatrix element offsets (k-chunk adds kc*16)
    int aoff[2];
    #pragma unroll
    for (int mt = 0; mt < 2; mt++)
        aoff[mt] = (m0 + mt * 16 + (lane & 15)) * STRIDE + ((lane >> 4) << 3);
    int boff[4];
    #pragma unroll
    for (int p = 0; p < 4; p++)
        boff[p] = (n0 + p * 16 + ((lane >> 4) << 3) + (lane & 7)) * STRIDE
                + (((lane >> 3) & 1) << 3);

    float acc[2][8][4];
    #pragma unroll
    for (int mt = 0; mt < 2; mt++)
        #pragma unroll
        for (int nt = 0; nt < 8; nt++)
            #pragma unroll
            for (int q = 0; q < 4; q++)
                acc[mt][nt][q] = 0.f;

    const uint32_t abase = smem_u32(smem + SO_A);
    const uint32_t bbase = smem_u32(smem + SO_B);

    #pragma unroll
    for (int kc = 0; kc < 8; kc++) {
        const int k0 = kc * 16;
        uint32_t a[2][4];
        #pragma unroll
        for (int mt = 0; mt < 2; mt++)
            LDSM_X4(a[mt], abase + (uint32_t)(aoff[mt] + k0) * 2);
        uint32_t b[4][4];
        #pragma unroll
        for (int p = 0; p < 4; p++)
            LDSM_X4(b[p], bbase + (uint32_t)(boff[p] + k0) * 2);
        #pragma unroll
        for (int mt = 0; mt < 2; mt++)
            #pragma unroll
            for (int p = 0; p < 4; p++) {
                mma_f16(acc[mt][2 * p],     a[mt], &b[p][0]);
                mma_f16(acc[mt][2 * p + 1], a[mt], &b[p][2]);
            }
    }

    // ---- epilogue: +b1 (jb==0), fp16 store to g_Ph ----
    const float* sb1 = (const float*)(smem + SO_B1);
    #pragma unroll
    for (int nt = 0; nt < 8; nt++) {
        const int j = n0 + nt * 8 + 2 * tig;             // even
        float bx = 0.f, by = 0.f;
        if (jb == 0) { bx = sb1[j]; by = sb1[j + 1]; }
        #pragma unroll
        for (int mt = 0; mt < 2; mt++) {
            const int node0 = tile * TILE_M + m0 + mt * 16 + gid;
            float* c = acc[mt][nt];
            if (node0 < nNodes) {
                __half2 hv = __floats2half2_rn(c[0] + bx, c[1] + by);
                *(__half2*)(g_Ph + (size_t)node0 * POUT + jb * 128 + j) = hv;
            }
            if (node0 + 8 < nNodes) {
                __half2 hv = __floats2half2_rn(c[2] + bx, c[3] + by);
                *(__half2*)(g_Ph + (size_t)(node0 + 8) * POUT + jb * 128 + j) = hv;
            }
        }
    }
}

// ------------------------------------------------------------------ edge stage
// 2 edges per warp; 16 lanes each, lane l covers hidden dims [8l, 8l+7].
__global__ __launch_bounds__(256) void edge_kernel(
    const int*   __restrict__ src,
    const int*   __restrict__ dst,
    const float* __restrict__ W2,
    const float* __restrict__ b2,
    float*       __restrict__ out,
    int E)
{
    const int gw   = (int)((blockIdx.x * 256u + threadIdx.x) >> 5);
    const int lane = threadIdx.x & 31;
    const int sub  = lane >> 4;
    const int l    = lane & 15;

    const int e0 = gw * 2;
    if (e0 >= E) return;              // whole warp out of range
    int e = e0 + sub;
    const bool valid = (e < E);
    if (e >= E) e = E - 1;            // keep warp converged for shfl

    // W2 slice: 2 vector loads (L1-resident) instead of 8 scalars
    const float4 w0 = *(const float4*)&W2[l * 8];
    const float4 w1 = *(const float4*)&W2[l * 8 + 4];

    // pair-load both edges' endpoints (e0 even -> 8B aligned)
    int s, d;
    if (e0 + 1 < E) {
        int2 sv = *(const int2*)(src + e0);
        int2 dv = *(const int2*)(dst + e0);
        s = sub ? sv.y : sv.x;
        d = sub ? dv.y : dv.x;
    } else {
        s = src[e];
        d = dst[e];
    }

    const uint4 pa = *(const uint4*)(g_Ph + (size_t)s * POUT + l * 8);
    const uint4 pb = *(const uint4*)(g_Ph + (size_t)d * POUT + 128 + l * 8);

    const __half2* ha = (const __half2*)&pa;
    const __half2* hb = (const __half2*)&pb;

    float2 f0 = __half22float2(ha[0]);
    float2 g0 = __half22float2(hb[0]);
    float2 f1 = __half22float2(ha[1]);
    float2 g1 = __half22float2(hb[1]);
    float2 f2 = __half22float2(ha[2]);
    float2 g2 = __half22float2(hb[2]);
    float2 f3 = __half22float2(ha[3]);
    float2 g3 = __half22float2(hb[3]);

    float acc;
    acc = fmaf(fmaxf(f0.x + g0.x, 0.f), w0.x, 0.f);
    acc = fmaf(fmaxf(f0.y + g0.y, 0.f), w0.y, acc);
    acc = fmaf(fmaxf(f1.x + g1.x, 0.f), w0.z, acc);
    acc = fmaf(fmaxf(f1.y + g1.y, 0.f), w0.w, acc);
    acc = fmaf(fmaxf(f2.x + g2.x, 0.f), w1.x, acc);
    acc = fmaf(fmaxf(f2.y + g2.y, 0.f), w1.y, acc);
    acc = fmaf(fmaxf(f3.x + g3.x, 0.f), w1.z, acc);
    acc = fmaf(fmaxf(f3.y + g3.y, 0.f), w1.w, acc);

    #pragma unroll
    for (int off = 8; off > 0; off >>= 1)
        acc += __shfl_down_sync(0xFFFFFFFFu, acc, off, 16);

    if (l == 0 && valid) {
        float z = acc + b2[0];
        out[e] = 1.0f / (1.0f + __expf(-z));
    }
}

// ---------------------------------------------------------------------- launch
extern "C" void kernel_launch(void* const* d_in, const int* in_sizes, int n_in,
                              void* d_out, int out_size)
{
    const int*   src = (const int*)  d_in[0];
    const int*   dst = (const int*)  d_in[1];
    const float* h   = (const float*)d_in[2];
    const float* W1  = (const float*)d_in[3];
    const float* b1  = (const float*)d_in[4];
    const float* W2  = (const float*)d_in[5];
    const float* b2  = (const float*)d_in[6];
    float* out = (float*)d_out;

    const int E      = in_sizes[0];
    const int nNodes = in_sizes[2] / FEATS;
    const int nTiles = (nNodes + TILE_M - 1) / TILE_M;

    cudaFuncSetAttribute(proj_mma, cudaFuncAttributeMaxDynamicSharedMemorySize, SMEM_TOTAL);
    proj_mma<<<dim3(nTiles, 2), 256, SMEM_TOTAL>>>(h, W1, b1, nNodes);

    const int nWarps  = (E + 1) / 2;
    const int nBlocks = (nWarps + 7) / 8;
    edge_kernel<<<nBlocks, 256>>>(src, dst, W2, b2, out, E);
}